// round 1
// baseline (speedup 1.0000x reference)
#include <cuda_runtime.h>
#include <cstdint>

// Problem shapes (fixed for this dataset entry)
#define BB 2
#define NN 4096
#define DD 768

// GEMM tiling
constexpr int BM = 128, BN = 128, BK = 32;   // block tile
// 8 warps: 4 along M (32 rows each), 2 along N (64 cols each)

// ---------------------------------------------------------------------------
// Scratch (device globals; no allocation allowed in kernel_launch)
// ---------------------------------------------------------------------------
__device__ float g_q[BB * NN * DD];                 // 25 MB
__device__ float g_k[BB * NN * DD];                 // 25 MB
__device__ float g_v[BB * NN * DD];                 // 25 MB
__device__ float g_s[(size_t)BB * NN * NN];         // 134 MB scores/probs

// ---------------------------------------------------------------------------
// Helpers
// ---------------------------------------------------------------------------
__device__ __forceinline__ uint32_t f2tf(float f) {
    uint32_t u;
    asm("cvt.rna.tf32.f32 %0, %1;" : "=r"(u) : "f"(f));
    return u;
}

// ---------------------------------------------------------------------------
// Generic TF32 tensor-core GEMM: C = alpha * A @ B  (+ optional B^T-on-load)
//   A: [M, K] row-major (fp32, converted to tf32 on smem fill)
//   B: if !TRANSB: [K, N] row-major. if TRANSB: [N, K] row-major, used as B^T.
//   C: [M, N] row-major fp32
// blockIdx.z selects the batch via the given element strides.
// All dims must be multiples of the tile sizes (true for every call here).
// ---------------------------------------------------------------------------
template <bool TRANSB>
__global__ __launch_bounds__(256, 2)
void gemm_tf32(const float* __restrict__ Ag, const float* __restrict__ Bg,
               float* __restrict__ Cg, int M, int Ncols, int K,
               size_t sA, size_t sB, size_t sC, float alpha)
{
    __shared__ __align__(16) uint32_t As[BM][BK + 4];  // row stride 36 -> conflict-free frags
    __shared__ __align__(16) uint32_t Bs[BK][BN + 4];  // row stride 132 -> conflict-free frags

    const int z = blockIdx.z;
    Ag += (size_t)z * sA;
    Bg += (size_t)z * sB;
    Cg += (size_t)z * sC;

    const int tid  = threadIdx.x;
    const int lane = tid & 31;
    const int warp = tid >> 5;
    const int wm = warp & 3;      // warp row (0..3), 32 rows each
    const int wn = warp >> 2;     // warp col (0..1), 64 cols each
    const int m0 = blockIdx.y * BM;
    const int n0 = blockIdx.x * BN;

    float acc[2][8][4];
#pragma unroll
    for (int mi = 0; mi < 2; mi++)
#pragma unroll
        for (int ni = 0; ni < 8; ni++)
#pragma unroll
            for (int r = 0; r < 4; r++) acc[mi][ni][r] = 0.f;

    for (int k0 = 0; k0 < K; k0 += BK) {
        // ---- load A tile: 128 x 32 floats = 1024 float4, 4 per thread ----
#pragma unroll
        for (int i = 0; i < 4; i++) {
            const int idx = tid + i * 256;
            const int r   = idx >> 3;
            const int c4  = (idx & 7) * 4;
            const float4 f = *(const float4*)(Ag + (size_t)(m0 + r) * K + k0 + c4);
            uint4 u = make_uint4(f2tf(f.x), f2tf(f.y), f2tf(f.z), f2tf(f.w));
            *(uint4*)&As[r][c4] = u;
        }
        // ---- load B tile ----
        if (!TRANSB) {
            // B[K,N] row-major: rows k0..k0+31, cols n0..n0+127
#pragma unroll
            for (int i = 0; i < 4; i++) {
                const int idx = tid + i * 256;
                const int r   = idx >> 5;          // 0..31
                const int c4  = (idx & 31) * 4;    // 0..124
                const float4 f = *(const float4*)(Bg + (size_t)(k0 + r) * Ncols + n0 + c4);
                uint4 u = make_uint4(f2tf(f.x), f2tf(f.y), f2tf(f.z), f2tf(f.w));
                *(uint4*)&Bs[r][c4] = u;
            }
        } else {
            // B[N,K] row-major; Bs[kk][nn] = B[n0+nn][k0+kk]
#pragma unroll
            for (int i = 0; i < 4; i++) {
                const int idx = tid + i * 256;
                const int nn  = idx >> 3;          // 0..127
                const int k4  = (idx & 7) * 4;     // 0..28
                const float4 f = *(const float4*)(Bg + (size_t)(n0 + nn) * K + k0 + k4);
                Bs[k4 + 0][nn] = f2tf(f.x);
                Bs[k4 + 1][nn] = f2tf(f.y);
                Bs[k4 + 2][nn] = f2tf(f.z);
                Bs[k4 + 3][nn] = f2tf(f.w);
            }
        }
        __syncthreads();

        // ---- compute: 4 k-steps of 8 ----
#pragma unroll
        for (int ks = 0; ks < BK; ks += 8) {
            uint32_t a[2][4];
            uint32_t b[8][2];
            const int ar = wm * 32 + (lane >> 2);
            const int ac = ks + (lane & 3);
#pragma unroll
            for (int mi = 0; mi < 2; mi++) {
                a[mi][0] = As[ar + mi * 16][ac];
                a[mi][1] = As[ar + mi * 16 + 8][ac];
                a[mi][2] = As[ar + mi * 16][ac + 4];
                a[mi][3] = As[ar + mi * 16 + 8][ac + 4];
            }
            const int br = ks + (lane & 3);
#pragma unroll
            for (int ni = 0; ni < 8; ni++) {
                const int bc = wn * 64 + ni * 8 + (lane >> 2);
                b[ni][0] = Bs[br][bc];
                b[ni][1] = Bs[br + 4][bc];
            }
#pragma unroll
            for (int mi = 0; mi < 2; mi++)
#pragma unroll
                for (int ni = 0; ni < 8; ni++) {
                    asm volatile(
                        "mma.sync.aligned.m16n8k8.row.col.f32.tf32.tf32.f32 "
                        "{%0,%1,%2,%3},{%4,%5,%6,%7},{%8,%9},{%0,%1,%2,%3};"
                        : "+f"(acc[mi][ni][0]), "+f"(acc[mi][ni][1]),
                          "+f"(acc[mi][ni][2]), "+f"(acc[mi][ni][3])
                        : "r"(a[mi][0]), "r"(a[mi][1]), "r"(a[mi][2]), "r"(a[mi][3]),
                          "r"(b[ni][0]), "r"(b[ni][1]));
                }
        }
        __syncthreads();
    }

    // ---- epilogue ----
#pragma unroll
    for (int mi = 0; mi < 2; mi++) {
        const int r = m0 + wm * 32 + mi * 16 + (lane >> 2);
#pragma unroll
        for (int ni = 0; ni < 8; ni++) {
            const int c = n0 + wn * 64 + ni * 8 + (lane & 3) * 2;
            float2 v0 = make_float2(alpha * acc[mi][ni][0], alpha * acc[mi][ni][1]);
            float2 v1 = make_float2(alpha * acc[mi][ni][2], alpha * acc[mi][ni][3]);
            *(float2*)(Cg + (size_t)r * Ncols + c)       = v0;
            *(float2*)(Cg + (size_t)(r + 8) * Ncols + c) = v1;
        }
    }
}

// ---------------------------------------------------------------------------
// In-place row softmax over rows of length NN (=4096). One block per row,
// 256 threads, 16 elements/thread held in registers (single global RW pass).
// ---------------------------------------------------------------------------
__global__ __launch_bounds__(256)
void softmax_rows(float* __restrict__ S)
{
    float* p = S + (size_t)blockIdx.x * NN;
    const int t = threadIdx.x;

    float v[16];
    float mx = -3.4e38f;
#pragma unroll
    for (int i = 0; i < 16; i++) {
        v[i] = p[t + i * 256];
        mx = fmaxf(mx, v[i]);
    }

    __shared__ float shm[8];
    __shared__ float shs[8];

#pragma unroll
    for (int o = 16; o; o >>= 1) mx = fmaxf(mx, __shfl_xor_sync(0xffffffffu, mx, o));
    if ((t & 31) == 0) shm[t >> 5] = mx;
    __syncthreads();
    mx = shm[0];
#pragma unroll
    for (int i = 1; i < 8; i++) mx = fmaxf(mx, shm[i]);

    float sum = 0.f;
#pragma unroll
    for (int i = 0; i < 16; i++) {
        v[i] = __expf(v[i] - mx);
        sum += v[i];
    }
#pragma unroll
    for (int o = 16; o; o >>= 1) sum += __shfl_xor_sync(0xffffffffu, sum, o);
    if ((t & 31) == 0) shs[t >> 5] = sum;
    __syncthreads();
    sum = 0.f;
#pragma unroll
    for (int i = 0; i < 8; i++) sum += shs[i];

    const float inv = 1.0f / sum;
#pragma unroll
    for (int i = 0; i < 16; i++) p[t + i * 256] = v[i] * inv;
}

// ---------------------------------------------------------------------------
// Launch: x -> (Q,K,V) -> S = QK^T/sqrt(D) -> softmax -> out = P V
// ---------------------------------------------------------------------------
extern "C" void kernel_launch(void* const* d_in, const int* in_sizes, int n_in,
                              void* d_out, int out_size)
{
    const float* x  = (const float*)d_in[0];
    const float* Wq = (const float*)d_in[1];
    const float* Wk = (const float*)d_in[2];
    const float* Wv = (const float*)d_in[3];
    float* out = (float*)d_out;

    float *q, *k, *v, *s;
    cudaGetSymbolAddress((void**)&q, g_q);
    cudaGetSymbolAddress((void**)&k, g_k);
    cudaGetSymbolAddress((void**)&v, g_v);
    cudaGetSymbolAddress((void**)&s, g_s);

    const float scale = 0.03608439182435161f;  // 1/sqrt(768)
    const dim3 thr(256);

    // QKV projections: [8192,768] @ [768,768], exact tiling 64x6 blocks
    const dim3 gQKV(DD / BN, (BB * NN) / BM, 1);
    gemm_tf32<false><<<gQKV, thr>>>(x, Wq, q, BB * NN, DD, DD, 0, 0, 0, 1.f);
    gemm_tf32<false><<<gQKV, thr>>>(x, Wk, k, BB * NN, DD, DD, 0, 0, 0, 1.f);
    gemm_tf32<false><<<gQKV, thr>>>(x, Wv, v, BB * NN, DD, DD, 0, 0, 0, 1.f);

    // Scores: per batch, [4096,4096] = Q @ K^T * scale
    gemm_tf32<true><<<dim3(NN / BN, NN / BM, BB), thr>>>(
        q, k, s, NN, NN, DD,
        (size_t)NN * DD, (size_t)NN * DD, (size_t)NN * NN, scale);

    // Row softmax over all 8192 rows (in place)
    softmax_rows<<<BB * NN, thr>>>(s);

    // Output: per batch, [4096,768] = P @ V
    gemm_tf32<false><<<dim3(DD / BN, NN / BM, BB), thr>>>(
        s, v, out, NN, DD, NN,
        (size_t)NN * NN, (size_t)NN * DD, (size_t)NN * DD, 1.f);
}

// round 3
// speedup vs baseline: 1.6834x; 1.6834x over previous
#include <cuda_runtime.h>
#include <cuda_fp16.h>
#include <cstdint>

#define BB 2
#define NN 4096
#define DD 768

constexpr int BM = 128, BN = 128, BK = 32;

// ---------------------------------------------------------------------------
// Scratch
// ---------------------------------------------------------------------------
__device__ float g_q[BB * NN * DD];
__device__ float g_k[BB * NN * DD];
__device__ float g_v[BB * NN * DD];
__device__ float g_s[(size_t)BB * NN * NN];

// ---------------------------------------------------------------------------
// Helpers
// ---------------------------------------------------------------------------
__device__ __forceinline__ uint32_t smem_u32(const void* p) {
    uint32_t a;
    asm("{ .reg .u64 t; cvta.to.shared.u64 t, %1; cvt.u32.u64 %0, t; }" : "=r"(a) : "l"(p));
    return a;
}
// swizzle for 64B rows: bits[5:4] ^= bits[8:7]
__device__ __forceinline__ uint32_t sw64(uint32_t o) { return o ^ ((o >> 3) & 0x30); }

__device__ __forceinline__ void ldm_x4(uint32_t* r, uint32_t a) {
    asm volatile("ldmatrix.sync.aligned.m8n8.x4.shared.b16 {%0,%1,%2,%3}, [%4];"
                 : "=r"(r[0]), "=r"(r[1]), "=r"(r[2]), "=r"(r[3]) : "r"(a));
}
__device__ __forceinline__ void mma16816(float* c, const uint32_t* a, const uint32_t* b) {
    asm volatile(
        "mma.sync.aligned.m16n8k16.row.col.f32.f16.f16.f32 "
        "{%0,%1,%2,%3},{%4,%5,%6,%7},{%8,%9},{%0,%1,%2,%3};"
        : "+f"(c[0]), "+f"(c[1]), "+f"(c[2]), "+f"(c[3])
        : "r"(a[0]), "r"(a[1]), "r"(a[2]), "r"(a[3]), "r"(b[0]), "r"(b[1]));
}
__device__ __forceinline__ uint32_t h2u(__half2 h) { return *(uint32_t*)&h; }

// ---------------------------------------------------------------------------
// fp16 tensor-core GEMM:  C = alpha * A @ op(B)
//   A: [M,K] row-major fp32 (cvt to fp16 on fill)
//   TRANSB: B [N,K] row-major (used as B^T).  else: B [K,N] row-major.
// CTA 128x128x32, 8 warps of 64x32, 2-stage smem double buffering.
// smem tiles stored as [rows][32 fp16] = 64B rows, SW64 swizzled; fragments
// via ldmatrix.x4 (conflict-free).
// ---------------------------------------------------------------------------
template <bool TRANSB>
__global__ __launch_bounds__(256, 2)
void gemm_h(const float* __restrict__ Ag, const float* __restrict__ Bg,
            float* __restrict__ Cg, int M, int Ncols, int K,
            size_t sAs, size_t sBs, size_t sCs, float alpha)
{
    __shared__ __align__(1024) __half sA[2][BM * BK];
    __shared__ __align__(1024) __half sB[2][BN * BK];

    const int tid  = threadIdx.x;
    const int lane = tid & 31;
    const int warp = tid >> 5;
    const int wm = warp >> 2;        // 0..1, 64 rows
    const int wn = warp & 3;         // 0..3, 32 cols
    const int z = blockIdx.z;
    Ag += (size_t)z * sAs;
    Bg += (size_t)z * sBs;
    Cg += (size_t)z * sCs;
    const int m0 = blockIdx.y * BM;
    const int n0 = blockIdx.x * BN;

    float acc[4][4][4];
#pragma unroll
    for (int mi = 0; mi < 4; mi++)
#pragma unroll
        for (int ni = 0; ni < 4; ni++)
#pragma unroll
            for (int r = 0; r < 4; r++) acc[mi][ni][r] = 0.f;

    // fill staging registers
    float4 fa[4];
    float4 fb[4];       // TRANSB path
    float  fbn[16];     // non-TRANSB path
    const int nnf = tid & 127;       // non-TRANSB: column within tile
    const int q0  = tid >> 7;        // non-TRANSB: k-quad base (0..1)

    auto LDGA = [&](int t) {
        const int k0 = t * BK;
#pragma unroll
        for (int i = 0; i < 4; i++) {
            const int f = tid + i * 256;
            fa[i] = *(const float4*)(Ag + (size_t)(m0 + (f >> 3)) * K + k0 + (f & 7) * 4);
        }
    };
    auto STSA = [&](int s) {
#pragma unroll
        for (int i = 0; i < 4; i++) {
            const int f = tid + i * 256;
            uint2 u;
            u.x = h2u(__floats2half2_rn(fa[i].x, fa[i].y));
            u.y = h2u(__floats2half2_rn(fa[i].z, fa[i].w));
            *(uint2*)((char*)sA[s] + sw64((f >> 3) * 64 + (f & 7) * 8)) = u;
        }
    };
    auto LDGB = [&](int t) {
        const int k0 = t * BK;
        if (TRANSB) {
#pragma unroll
            for (int i = 0; i < 4; i++) {
                const int f = tid + i * 256;
                fb[i] = *(const float4*)(Bg + (size_t)(n0 + (f >> 3)) * K + k0 + (f & 7) * 4);
            }
        } else {
            // gather 4 k-consecutive values per quad at fixed column (coalesced across lanes)
#pragma unroll
            for (int i = 0; i < 4; i++) {
                const int q = q0 + 2 * i;
                const float* src = Bg + (size_t)(k0 + q * 4) * Ncols + n0 + nnf;
                fbn[i * 4 + 0] = src[0];
                fbn[i * 4 + 1] = src[Ncols];
                fbn[i * 4 + 2] = src[2 * Ncols];
                fbn[i * 4 + 3] = src[3 * Ncols];
            }
        }
    };
    auto STSB = [&](int s) {
        if (TRANSB) {
#pragma unroll
            for (int i = 0; i < 4; i++) {
                const int f = tid + i * 256;
                uint2 u;
                u.x = h2u(__floats2half2_rn(fb[i].x, fb[i].y));
                u.y = h2u(__floats2half2_rn(fb[i].z, fb[i].w));
                *(uint2*)((char*)sB[s] + sw64((f >> 3) * 64 + (f & 7) * 8)) = u;
            }
        } else {
#pragma unroll
            for (int i = 0; i < 4; i++) {
                const int q = q0 + 2 * i;
                uint2 u;
                u.x = h2u(__floats2half2_rn(fbn[i * 4 + 0], fbn[i * 4 + 1]));
                u.y = h2u(__floats2half2_rn(fbn[i * 4 + 2], fbn[i * 4 + 3]));
                *(uint2*)((char*)sB[s] + sw64(nnf * 64 + q * 8)) = u;
            }
        }
    };

    // fragment lane addressing (constant across tiles)
    const int mrow  = wm * 64 + (lane & 15);
    const int acolb = (lane & 16);                       // A: k-seg byte offset (+8 elems)
    const int nrow  = wn * 32 + (lane & 7) + ((lane & 16) >> 1);
    const int bcolb = (lane & 8) << 1;                   // B: k-seg byte offset

    auto KSTEP = [&](int s, int ks) {
        const uint32_t baseA = smem_u32(sA[s]);
        const uint32_t baseB = smem_u32(sB[s]);
        uint32_t a[4][4], b[2][4];
#pragma unroll
        for (int mi = 0; mi < 4; mi++)
            ldm_x4(a[mi], baseA + sw64((mrow + mi * 16) * 64 + ks * 2 + acolb));
#pragma unroll
        for (int n2 = 0; n2 < 2; n2++)
            ldm_x4(b[n2], baseB + sw64((nrow + n2 * 16) * 64 + ks * 2 + bcolb));
#pragma unroll
        for (int mi = 0; mi < 4; mi++)
#pragma unroll
            for (int ni = 0; ni < 4; ni++)
                mma16816(acc[mi][ni], a[mi], &b[ni >> 1][(ni & 1) * 2]);
    };

    // ---- pipeline ----
    LDGA(0); LDGB(0);
    STSA(0); STSB(0);
    __syncthreads();

    const int NT = K / BK;
    for (int t = 0; t < NT; t++) {
        const int s = t & 1;
        const bool more = (t + 1 < NT);
        if (more) LDGA(t + 1);
        KSTEP(s, 0);
        if (more) { STSA(s ^ 1); LDGB(t + 1); }
        KSTEP(s, 16);
        if (more) STSB(s ^ 1);
        __syncthreads();
    }

    // ---- epilogue ----
#pragma unroll
    for (int mi = 0; mi < 4; mi++) {
        const int r = m0 + wm * 64 + mi * 16 + (lane >> 2);
#pragma unroll
        for (int ni = 0; ni < 4; ni++) {
            const int c = n0 + wn * 32 + ni * 8 + (lane & 3) * 2;
            *(float2*)(Cg + (size_t)r * Ncols + c) =
                make_float2(alpha * acc[mi][ni][0], alpha * acc[mi][ni][1]);
            *(float2*)(Cg + (size_t)(r + 8) * Ncols + c) =
                make_float2(alpha * acc[mi][ni][2], alpha * acc[mi][ni][3]);
        }
    }
}

// ---------------------------------------------------------------------------
// Row softmax (in place), rows of 4096, float4 I/O.
// ---------------------------------------------------------------------------
__global__ __launch_bounds__(256)
void softmax_rows(float* __restrict__ S)
{
    float4* p = (float4*)(S + (size_t)blockIdx.x * NN);
    const int t = threadIdx.x;

    float4 v[4];
    float mx = -3.4e38f;
#pragma unroll
    for (int i = 0; i < 4; i++) {
        v[i] = p[t + i * 256];
        mx = fmaxf(mx, fmaxf(fmaxf(v[i].x, v[i].y), fmaxf(v[i].z, v[i].w)));
    }

    __shared__ float shm[8], shs[8];
#pragma unroll
    for (int o = 16; o; o >>= 1) mx = fmaxf(mx, __shfl_xor_sync(0xffffffffu, mx, o));
    if ((t & 31) == 0) shm[t >> 5] = mx;
    __syncthreads();
    mx = shm[0];
#pragma unroll
    for (int i = 1; i < 8; i++) mx = fmaxf(mx, shm[i]);

    float sum = 0.f;
#pragma unroll
    for (int i = 0; i < 4; i++) {
        v[i].x = __expf(v[i].x - mx); v[i].y = __expf(v[i].y - mx);
        v[i].z = __expf(v[i].z - mx); v[i].w = __expf(v[i].w - mx);
        sum += v[i].x + v[i].y + v[i].z + v[i].w;
    }
#pragma unroll
    for (int o = 16; o; o >>= 1) sum += __shfl_xor_sync(0xffffffffu, sum, o);
    if ((t & 31) == 0) shs[t >> 5] = sum;
    __syncthreads();
    sum = 0.f;
#pragma unroll
    for (int i = 0; i < 8; i++) sum += shs[i];

    const float inv = 1.0f / sum;
#pragma unroll
    for (int i = 0; i < 4; i++) {
        v[i].x *= inv; v[i].y *= inv; v[i].z *= inv; v[i].w *= inv;
        p[t + i * 256] = v[i];
    }
}

// ---------------------------------------------------------------------------
extern "C" void kernel_launch(void* const* d_in, const int* in_sizes, int n_in,
                              void* d_out, int out_size)
{
    const float* x  = (const float*)d_in[0];
    const float* Wq = (const float*)d_in[1];
    const float* Wk = (const float*)d_in[2];
    const float* Wv = (const float*)d_in[3];
    float* out = (float*)d_out;

    float *q, *k, *v, *s;
    cudaGetSymbolAddress((void**)&q, g_q);
    cudaGetSymbolAddress((void**)&k, g_k);
    cudaGetSymbolAddress((void**)&v, g_v);
    cudaGetSymbolAddress((void**)&s, g_s);

    const float scale = 0.03608439182435161f;  // 1/sqrt(768)
    const dim3 thr(256);

    // QKV projections: [8192,768] @ [768,768]  (B = [K,N], non-trans)
    const dim3 gQKV(DD / BN, (BB * NN) / BM, 1);
    gemm_h<false><<<gQKV, thr>>>(x, Wq, q, BB * NN, DD, DD, 0, 0, 0, 1.f);
    gemm_h<false><<<gQKV, thr>>>(x, Wk, k, BB * NN, DD, DD, 0, 0, 0, 1.f);
    gemm_h<false><<<gQKV, thr>>>(x, Wv, v, BB * NN, DD, DD, 0, 0, 0, 1.f);

    // Scores: per batch [4096,4096] = Q @ K^T * scale  (B = [N,K], trans)
    gemm_h<true><<<dim3(NN / BN, NN / BM, BB), thr>>>(
        q, k, s, NN, NN, DD,
        (size_t)NN * DD, (size_t)NN * DD, (size_t)NN * NN, scale);

    // Row softmax (in place)
    softmax_rows<<<BB * NN, thr>>>(s);

    // Output: per batch [4096,768] = P @ V  (B = [K,N], non-trans)
    gemm_h<false><<<dim3(DD / BN, NN / BM, BB), thr>>>(
        s, v, out, NN, DD, NN,
        (size_t)NN * NN, (size_t)NN * DD, (size_t)NN * DD, 1.f);
}

// round 4
// speedup vs baseline: 1.6856x; 1.0013x over previous
#include <cuda_runtime.h>
#include <cuda_fp16.h>
#include <cstdint>

#define BB 2
#define NN 4096
#define DD 768

constexpr int BM = 128, BN = 128, BK = 32;

// ---------------------------------------------------------------------------
// Scratch
// ---------------------------------------------------------------------------
__device__ float g_q[BB * NN * DD];
__device__ float g_k[BB * NN * DD];
__device__ float g_v[BB * NN * DD];
__device__ float g_s[(size_t)BB * NN * NN];

// ---------------------------------------------------------------------------
// Helpers
// ---------------------------------------------------------------------------
__device__ __forceinline__ uint32_t smem_u32(const void* p) {
    uint32_t a;
    asm("{ .reg .u64 t; cvta.to.shared.u64 t, %1; cvt.u32.u64 %0, t; }" : "=r"(a) : "l"(p));
    return a;
}
// swizzle for 64B rows: bits[5:4] ^= bits[8:7]
__device__ __forceinline__ uint32_t sw64(uint32_t o) { return o ^ ((o >> 3) & 0x30); }

__device__ __forceinline__ void ldm_x4(uint32_t* r, uint32_t a) {
    asm volatile("ldmatrix.sync.aligned.m8n8.x4.shared.b16 {%0,%1,%2,%3}, [%4];"
                 : "=r"(r[0]), "=r"(r[1]), "=r"(r[2]), "=r"(r[3]) : "r"(a));
}
__device__ __forceinline__ void mma16816(float* c, const uint32_t* a, const uint32_t* b) {
    asm volatile(
        "mma.sync.aligned.m16n8k16.row.col.f32.f16.f16.f32 "
        "{%0,%1,%2,%3},{%4,%5,%6,%7},{%8,%9},{%0,%1,%2,%3};"
        : "+f"(c[0]), "+f"(c[1]), "+f"(c[2]), "+f"(c[3])
        : "r"(a[0]), "r"(a[1]), "r"(a[2]), "r"(a[3]), "r"(b[0]), "r"(b[1]));
}
__device__ __forceinline__ uint32_t h2u(__half2 h) { return *(uint32_t*)&h; }

// ---------------------------------------------------------------------------
// fp16 tensor-core GEMM:  C = alpha * A @ op(B)
//   A: [M,K] row-major fp32 (cvt to fp16 on fill)
//   TRANSB: B [N,K] row-major (used as B^T).  else: B [K,N] row-major.
// CTA 128x128x32, 8 warps of 64x32, 2-stage smem double buffering.
// smem tiles stored as [rows][32 fp16] = 64B rows, SW64 swizzled; fragments
// via ldmatrix.x4 (conflict-free).
// ---------------------------------------------------------------------------
template <bool TRANSB>
__global__ __launch_bounds__(256, 2)
void gemm_h(const float* __restrict__ Ag, const float* __restrict__ Bg,
            float* __restrict__ Cg, int M, int Ncols, int K,
            size_t sAs, size_t sBs, size_t sCs, float alpha)
{
    __shared__ __align__(1024) __half sA[2][BM * BK];
    __shared__ __align__(1024) __half sB[2][BN * BK];

    const int tid  = threadIdx.x;
    const int lane = tid & 31;
    const int warp = tid >> 5;
    const int wm = warp >> 2;        // 0..1, 64 rows
    const int wn = warp & 3;         // 0..3, 32 cols
    const int z = blockIdx.z;
    Ag += (size_t)z * sAs;
    Bg += (size_t)z * sBs;
    Cg += (size_t)z * sCs;
    const int m0 = blockIdx.y * BM;
    const int n0 = blockIdx.x * BN;

    float acc[4][4][4];
#pragma unroll
    for (int mi = 0; mi < 4; mi++)
#pragma unroll
        for (int ni = 0; ni < 4; ni++)
#pragma unroll
            for (int r = 0; r < 4; r++) acc[mi][ni][r] = 0.f;

    // fill staging registers
    float4 fa[4];
    float4 fb[4];       // TRANSB path
    float  fbn[16];     // non-TRANSB path
    const int nnf = tid & 127;       // non-TRANSB: column within tile
    const int q0  = tid >> 7;        // non-TRANSB: k-quad base (0..1)

    auto LDGA = [&](int t) {
        const int k0 = t * BK;
#pragma unroll
        for (int i = 0; i < 4; i++) {
            const int f = tid + i * 256;
            fa[i] = *(const float4*)(Ag + (size_t)(m0 + (f >> 3)) * K + k0 + (f & 7) * 4);
        }
    };
    auto STSA = [&](int s) {
#pragma unroll
        for (int i = 0; i < 4; i++) {
            const int f = tid + i * 256;
            uint2 u;
            u.x = h2u(__floats2half2_rn(fa[i].x, fa[i].y));
            u.y = h2u(__floats2half2_rn(fa[i].z, fa[i].w));
            *(uint2*)((char*)sA[s] + sw64((f >> 3) * 64 + (f & 7) * 8)) = u;
        }
    };
    auto LDGB = [&](int t) {
        const int k0 = t * BK;
        if (TRANSB) {
#pragma unroll
            for (int i = 0; i < 4; i++) {
                const int f = tid + i * 256;
                fb[i] = *(const float4*)(Bg + (size_t)(n0 + (f >> 3)) * K + k0 + (f & 7) * 4);
            }
        } else {
            // gather 4 k-consecutive values per quad at fixed column (coalesced across lanes)
#pragma unroll
            for (int i = 0; i < 4; i++) {
                const int q = q0 + 2 * i;
                const float* src = Bg + (size_t)(k0 + q * 4) * Ncols + n0 + nnf;
                fbn[i * 4 + 0] = src[0];
                fbn[i * 4 + 1] = src[Ncols];
                fbn[i * 4 + 2] = src[2 * Ncols];
                fbn[i * 4 + 3] = src[3 * Ncols];
            }
        }
    };
    auto STSB = [&](int s) {
        if (TRANSB) {
#pragma unroll
            for (int i = 0; i < 4; i++) {
                const int f = tid + i * 256;
                uint2 u;
                u.x = h2u(__floats2half2_rn(fb[i].x, fb[i].y));
                u.y = h2u(__floats2half2_rn(fb[i].z, fb[i].w));
                *(uint2*)((char*)sB[s] + sw64((f >> 3) * 64 + (f & 7) * 8)) = u;
            }
        } else {
#pragma unroll
            for (int i = 0; i < 4; i++) {
                const int q = q0 + 2 * i;
                uint2 u;
                u.x = h2u(__floats2half2_rn(fbn[i * 4 + 0], fbn[i * 4 + 1]));
                u.y = h2u(__floats2half2_rn(fbn[i * 4 + 2], fbn[i * 4 + 3]));
                *(uint2*)((char*)sB[s] + sw64(nnf * 64 + q * 8)) = u;
            }
        }
    };

    // fragment lane addressing (constant across tiles)
    const int mrow  = wm * 64 + (lane & 15);
    const int acolb = (lane & 16);                       // A: k-seg byte offset (+8 elems)
    const int nrow  = wn * 32 + (lane & 7) + ((lane & 16) >> 1);
    const int bcolb = (lane & 8) << 1;                   // B: k-seg byte offset

    auto KSTEP = [&](int s, int ks) {
        const uint32_t baseA = smem_u32(sA[s]);
        const uint32_t baseB = smem_u32(sB[s]);
        uint32_t a[4][4], b[2][4];
#pragma unroll
        for (int mi = 0; mi < 4; mi++)
            ldm_x4(a[mi], baseA + sw64((mrow + mi * 16) * 64 + ks * 2 + acolb));
#pragma unroll
        for (int n2 = 0; n2 < 2; n2++)
            ldm_x4(b[n2], baseB + sw64((nrow + n2 * 16) * 64 + ks * 2 + bcolb));
#pragma unroll
        for (int mi = 0; mi < 4; mi++)
#pragma unroll
            for (int ni = 0; ni < 4; ni++)
                mma16816(acc[mi][ni], a[mi], &b[ni >> 1][(ni & 1) * 2]);
    };

    // ---- pipeline ----
    LDGA(0); LDGB(0);
    STSA(0); STSB(0);
    __syncthreads();

    const int NT = K / BK;
    for (int t = 0; t < NT; t++) {
        const int s = t & 1;
        const bool more = (t + 1 < NT);
        if (more) LDGA(t + 1);
        KSTEP(s, 0);
        if (more) { STSA(s ^ 1); LDGB(t + 1); }
        KSTEP(s, 16);
        if (more) STSB(s ^ 1);
        __syncthreads();
    }

    // ---- epilogue ----
#pragma unroll
    for (int mi = 0; mi < 4; mi++) {
        const int r = m0 + wm * 64 + mi * 16 + (lane >> 2);
#pragma unroll
        for (int ni = 0; ni < 4; ni++) {
            const int c = n0 + wn * 32 + ni * 8 + (lane & 3) * 2;
            *(float2*)(Cg + (size_t)r * Ncols + c) =
                make_float2(alpha * acc[mi][ni][0], alpha * acc[mi][ni][1]);
            *(float2*)(Cg + (size_t)(r + 8) * Ncols + c) =
                make_float2(alpha * acc[mi][ni][2], alpha * acc[mi][ni][3]);
        }
    }
}

// ---------------------------------------------------------------------------
// Row softmax (in place), rows of 4096, float4 I/O.
// ---------------------------------------------------------------------------
__global__ __launch_bounds__(256)
void softmax_rows(float* __restrict__ S)
{
    float4* p = (float4*)(S + (size_t)blockIdx.x * NN);
    const int t = threadIdx.x;

    float4 v[4];
    float mx = -3.4e38f;
#pragma unroll
    for (int i = 0; i < 4; i++) {
        v[i] = p[t + i * 256];
        mx = fmaxf(mx, fmaxf(fmaxf(v[i].x, v[i].y), fmaxf(v[i].z, v[i].w)));
    }

    __shared__ float shm[8], shs[8];
#pragma unroll
    for (int o = 16; o; o >>= 1) mx = fmaxf(mx, __shfl_xor_sync(0xffffffffu, mx, o));
    if ((t & 31) == 0) shm[t >> 5] = mx;
    __syncthreads();
    mx = shm[0];
#pragma unroll
    for (int i = 1; i < 8; i++) mx = fmaxf(mx, shm[i]);

    float sum = 0.f;
#pragma unroll
    for (int i = 0; i < 4; i++) {
        v[i].x = __expf(v[i].x - mx); v[i].y = __expf(v[i].y - mx);
        v[i].z = __expf(v[i].z - mx); v[i].w = __expf(v[i].w - mx);
        sum += v[i].x + v[i].y + v[i].z + v[i].w;
    }
#pragma unroll
    for (int o = 16; o; o >>= 1) sum += __shfl_xor_sync(0xffffffffu, sum, o);
    if ((t & 31) == 0) shs[t >> 5] = sum;
    __syncthreads();
    sum = 0.f;
#pragma unroll
    for (int i = 0; i < 8; i++) sum += shs[i];

    const float inv = 1.0f / sum;
#pragma unroll
    for (int i = 0; i < 4; i++) {
        v[i].x *= inv; v[i].y *= inv; v[i].z *= inv; v[i].w *= inv;
        p[t + i * 256] = v[i];
    }
}

// ---------------------------------------------------------------------------
extern "C" void kernel_launch(void* const* d_in, const int* in_sizes, int n_in,
                              void* d_out, int out_size)
{
    const float* x  = (const float*)d_in[0];
    const float* Wq = (const float*)d_in[1];
    const float* Wk = (const float*)d_in[2];
    const float* Wv = (const float*)d_in[3];
    float* out = (float*)d_out;

    float *q, *k, *v, *s;
    cudaGetSymbolAddress((void**)&q, g_q);
    cudaGetSymbolAddress((void**)&k, g_k);
    cudaGetSymbolAddress((void**)&v, g_v);
    cudaGetSymbolAddress((void**)&s, g_s);

    const float scale = 0.03608439182435161f;  // 1/sqrt(768)
    const dim3 thr(256);

    // QKV projections: [8192,768] @ [768,768]  (B = [K,N], non-trans)
    const dim3 gQKV(DD / BN, (BB * NN) / BM, 1);
    gemm_h<false><<<gQKV, thr>>>(x, Wq, q, BB * NN, DD, DD, 0, 0, 0, 1.f);
    gemm_h<false><<<gQKV, thr>>>(x, Wk, k, BB * NN, DD, DD, 0, 0, 0, 1.f);
    gemm_h<false><<<gQKV, thr>>>(x, Wv, v, BB * NN, DD, DD, 0, 0, 0, 1.f);

    // Scores: per batch [4096,4096] = Q @ K^T * scale  (B = [N,K], trans)
    gemm_h<true><<<dim3(NN / BN, NN / BM, BB), thr>>>(
        q, k, s, NN, NN, DD,
        (size_t)NN * DD, (size_t)NN * DD, (size_t)NN * NN, scale);

    // Row softmax (in place)
    softmax_rows<<<BB * NN, thr>>>(s);

    // Output: per batch [4096,768] = P @ V  (B = [K,N], non-trans)
    gemm_h<false><<<dim3(DD / BN, NN / BM, BB), thr>>>(
        s, v, out, NN, DD, NN,
        (size_t)NN * NN, (size_t)NN * DD, (size_t)NN * DD, 1.f);
}

// round 5
// speedup vs baseline: 1.6917x; 1.0036x over previous
#include <cuda_runtime.h>
#include <cuda_fp16.h>
#include <cstdint>

#define BB 2
#define NN 4096
#define DD 768

constexpr int BM = 128, BN = 128, BK = 32;

// ---------------------------------------------------------------------------
// Scratch
// ---------------------------------------------------------------------------
__device__ float g_q[BB * NN * DD];
__device__ float g_k[BB * NN * DD];
__device__ float g_v[BB * NN * DD];
__device__ float g_s[(size_t)BB * NN * NN];

// ---------------------------------------------------------------------------
// Helpers
// ---------------------------------------------------------------------------
__device__ __forceinline__ uint32_t smem_u32(const void* p) {
    uint32_t a;
    asm("{ .reg .u64 t; cvta.to.shared.u64 t, %1; cvt.u32.u64 %0, t; }" : "=r"(a) : "l"(p));
    return a;
}
// swizzle for 64B rows: bits[5:4] ^= bits[8:7]
__device__ __forceinline__ uint32_t sw64(uint32_t o) { return o ^ ((o >> 3) & 0x30); }

__device__ __forceinline__ void ldm_x4(uint32_t* r, uint32_t a) {
    asm volatile("ldmatrix.sync.aligned.m8n8.x4.shared.b16 {%0,%1,%2,%3}, [%4];"
                 : "=r"(r[0]), "=r"(r[1]), "=r"(r[2]), "=r"(r[3]) : "r"(a));
}
__device__ __forceinline__ void mma16816(float* c, const uint32_t* a, const uint32_t* b) {
    asm volatile(
        "mma.sync.aligned.m16n8k16.row.col.f32.f16.f16.f32 "
        "{%0,%1,%2,%3},{%4,%5,%6,%7},{%8,%9},{%0,%1,%2,%3};"
        : "+f"(c[0]), "+f"(c[1]), "+f"(c[2]), "+f"(c[3])
        : "r"(a[0]), "r"(a[1]), "r"(a[2]), "r"(a[3]), "r"(b[0]), "r"(b[1]));
}
__device__ __forceinline__ uint32_t h2u(__half2 h) { return *(uint32_t*)&h; }

// ---------------------------------------------------------------------------
// fp16 tensor-core GEMM:  C = alpha * A @ op(B)
//   A: [M,K] row-major fp32 (cvt to fp16 on fill)
//   TRANSB: B [N,K] row-major (used as B^T).  else: B [K,N] row-major.
// CTA 128x128x32, 8 warps of 64x32, 2-stage smem double buffering.
// smem tiles stored as [rows][32 fp16] = 64B rows, SW64 swizzled; fragments
// via ldmatrix.x4 (conflict-free).
// ---------------------------------------------------------------------------
template <bool TRANSB>
__global__ __launch_bounds__(256, 2)
void gemm_h(const float* __restrict__ Ag, const float* __restrict__ Bg,
            float* __restrict__ Cg, int M, int Ncols, int K,
            size_t sAs, size_t sBs, size_t sCs, float alpha)
{
    __shared__ __align__(1024) __half sA[2][BM * BK];
    __shared__ __align__(1024) __half sB[2][BN * BK];

    const int tid  = threadIdx.x;
    const int lane = tid & 31;
    const int warp = tid >> 5;
    const int wm = warp >> 2;        // 0..1, 64 rows
    const int wn = warp & 3;         // 0..3, 32 cols
    const int z = blockIdx.z;
    Ag += (size_t)z * sAs;
    Bg += (size_t)z * sBs;
    Cg += (size_t)z * sCs;
    const int m0 = blockIdx.y * BM;
    const int n0 = blockIdx.x * BN;

    float acc[4][4][4];
#pragma unroll
    for (int mi = 0; mi < 4; mi++)
#pragma unroll
        for (int ni = 0; ni < 4; ni++)
#pragma unroll
            for (int r = 0; r < 4; r++) acc[mi][ni][r] = 0.f;

    // fill staging registers
    float4 fa[4];
    float4 fb[4];       // TRANSB path
    float  fbn[16];     // non-TRANSB path
    const int nnf = tid & 127;       // non-TRANSB: column within tile
    const int q0  = tid >> 7;        // non-TRANSB: k-quad base (0..1)

    auto LDGA = [&](int t) {
        const int k0 = t * BK;
#pragma unroll
        for (int i = 0; i < 4; i++) {
            const int f = tid + i * 256;
            fa[i] = *(const float4*)(Ag + (size_t)(m0 + (f >> 3)) * K + k0 + (f & 7) * 4);
        }
    };
    auto STSA = [&](int s) {
#pragma unroll
        for (int i = 0; i < 4; i++) {
            const int f = tid + i * 256;
            uint2 u;
            u.x = h2u(__floats2half2_rn(fa[i].x, fa[i].y));
            u.y = h2u(__floats2half2_rn(fa[i].z, fa[i].w));
            *(uint2*)((char*)sA[s] + sw64((f >> 3) * 64 + (f & 7) * 8)) = u;
        }
    };
    auto LDGB = [&](int t) {
        const int k0 = t * BK;
        if (TRANSB) {
#pragma unroll
            for (int i = 0; i < 4; i++) {
                const int f = tid + i * 256;
                fb[i] = *(const float4*)(Bg + (size_t)(n0 + (f >> 3)) * K + k0 + (f & 7) * 4);
            }
        } else {
            // gather 4 k-consecutive values per quad at fixed column (coalesced across lanes)
#pragma unroll
            for (int i = 0; i < 4; i++) {
                const int q = q0 + 2 * i;
                const float* src = Bg + (size_t)(k0 + q * 4) * Ncols + n0 + nnf;
                fbn[i * 4 + 0] = src[0];
                fbn[i * 4 + 1] = src[Ncols];
                fbn[i * 4 + 2] = src[2 * Ncols];
                fbn[i * 4 + 3] = src[3 * Ncols];
            }
        }
    };
    auto STSB = [&](int s) {
        if (TRANSB) {
#pragma unroll
            for (int i = 0; i < 4; i++) {
                const int f = tid + i * 256;
                uint2 u;
                u.x = h2u(__floats2half2_rn(fb[i].x, fb[i].y));
                u.y = h2u(__floats2half2_rn(fb[i].z, fb[i].w));
                *(uint2*)((char*)sB[s] + sw64((f >> 3) * 64 + (f & 7) * 8)) = u;
            }
        } else {
#pragma unroll
            for (int i = 0; i < 4; i++) {
                const int q = q0 + 2 * i;
                uint2 u;
                u.x = h2u(__floats2half2_rn(fbn[i * 4 + 0], fbn[i * 4 + 1]));
                u.y = h2u(__floats2half2_rn(fbn[i * 4 + 2], fbn[i * 4 + 3]));
                *(uint2*)((char*)sB[s] + sw64(nnf * 64 + q * 8)) = u;
            }
        }
    };

    // fragment lane addressing (constant across tiles)
    const int mrow  = wm * 64 + (lane & 15);
    const int acolb = (lane & 16);                       // A: k-seg byte offset (+8 elems)
    const int nrow  = wn * 32 + (lane & 7) + ((lane & 16) >> 1);
    const int bcolb = (lane & 8) << 1;                   // B: k-seg byte offset

    auto KSTEP = [&](int s, int ks) {
        const uint32_t baseA = smem_u32(sA[s]);
        const uint32_t baseB = smem_u32(sB[s]);
        uint32_t a[4][4], b[2][4];
#pragma unroll
        for (int mi = 0; mi < 4; mi++)
            ldm_x4(a[mi], baseA + sw64((mrow + mi * 16) * 64 + ks * 2 + acolb));
#pragma unroll
        for (int n2 = 0; n2 < 2; n2++)
            ldm_x4(b[n2], baseB + sw64((nrow + n2 * 16) * 64 + ks * 2 + bcolb));
#pragma unroll
        for (int mi = 0; mi < 4; mi++)
#pragma unroll
            for (int ni = 0; ni < 4; ni++)
                mma16816(acc[mi][ni], a[mi], &b[ni >> 1][(ni & 1) * 2]);
    };

    // ---- pipeline ----
    LDGA(0); LDGB(0);
    STSA(0); STSB(0);
    __syncthreads();

    const int NT = K / BK;
    for (int t = 0; t < NT; t++) {
        const int s = t & 1;
        const bool more = (t + 1 < NT);
        if (more) LDGA(t + 1);
        KSTEP(s, 0);
        if (more) { STSA(s ^ 1); LDGB(t + 1); }
        KSTEP(s, 16);
        if (more) STSB(s ^ 1);
        __syncthreads();
    }

    // ---- epilogue ----
#pragma unroll
    for (int mi = 0; mi < 4; mi++) {
        const int r = m0 + wm * 64 + mi * 16 + (lane >> 2);
#pragma unroll
        for (int ni = 0; ni < 4; ni++) {
            const int c = n0 + wn * 32 + ni * 8 + (lane & 3) * 2;
            *(float2*)(Cg + (size_t)r * Ncols + c) =
                make_float2(alpha * acc[mi][ni][0], alpha * acc[mi][ni][1]);
            *(float2*)(Cg + (size_t)(r + 8) * Ncols + c) =
                make_float2(alpha * acc[mi][ni][2], alpha * acc[mi][ni][3]);
        }
    }
}

// ---------------------------------------------------------------------------
// Row softmax (in place), rows of 4096, float4 I/O.
// ---------------------------------------------------------------------------
__global__ __launch_bounds__(256)
void softmax_rows(float* __restrict__ S)
{
    float4* p = (float4*)(S + (size_t)blockIdx.x * NN);
    const int t = threadIdx.x;

    float4 v[4];
    float mx = -3.4e38f;
#pragma unroll
    for (int i = 0; i < 4; i++) {
        v[i] = p[t + i * 256];
        mx = fmaxf(mx, fmaxf(fmaxf(v[i].x, v[i].y), fmaxf(v[i].z, v[i].w)));
    }

    __shared__ float shm[8], shs[8];
#pragma unroll
    for (int o = 16; o; o >>= 1) mx = fmaxf(mx, __shfl_xor_sync(0xffffffffu, mx, o));
    if ((t & 31) == 0) shm[t >> 5] = mx;
    __syncthreads();
    mx = shm[0];
#pragma unroll
    for (int i = 1; i < 8; i++) mx = fmaxf(mx, shm[i]);

    float sum = 0.f;
#pragma unroll
    for (int i = 0; i < 4; i++) {
        v[i].x = __expf(v[i].x - mx); v[i].y = __expf(v[i].y - mx);
        v[i].z = __expf(v[i].z - mx); v[i].w = __expf(v[i].w - mx);
        sum += v[i].x + v[i].y + v[i].z + v[i].w;
    }
#pragma unroll
    for (int o = 16; o; o >>= 1) sum += __shfl_xor_sync(0xffffffffu, sum, o);
    if ((t & 31) == 0) shs[t >> 5] = sum;
    __syncthreads();
    sum = 0.f;
#pragma unroll
    for (int i = 0; i < 8; i++) sum += shs[i];

    const float inv = 1.0f / sum;
#pragma unroll
    for (int i = 0; i < 4; i++) {
        v[i].x *= inv; v[i].y *= inv; v[i].z *= inv; v[i].w *= inv;
        p[t + i * 256] = v[i];
    }
}

// ---------------------------------------------------------------------------
extern "C" void kernel_launch(void* const* d_in, const int* in_sizes, int n_in,
                              void* d_out, int out_size)
{
    const float* x  = (const float*)d_in[0];
    const float* Wq = (const float*)d_in[1];
    const float* Wk = (const float*)d_in[2];
    const float* Wv = (const float*)d_in[3];
    float* out = (float*)d_out;

    float *q, *k, *v, *s;
    cudaGetSymbolAddress((void**)&q, g_q);
    cudaGetSymbolAddress((void**)&k, g_k);
    cudaGetSymbolAddress((void**)&v, g_v);
    cudaGetSymbolAddress((void**)&s, g_s);

    const float scale = 0.03608439182435161f;  // 1/sqrt(768)
    const dim3 thr(256);

    // QKV projections: [8192,768] @ [768,768]  (B = [K,N], non-trans)
    const dim3 gQKV(DD / BN, (BB * NN) / BM, 1);
    gemm_h<false><<<gQKV, thr>>>(x, Wq, q, BB * NN, DD, DD, 0, 0, 0, 1.f);
    gemm_h<false><<<gQKV, thr>>>(x, Wk, k, BB * NN, DD, DD, 0, 0, 0, 1.f);
    gemm_h<false><<<gQKV, thr>>>(x, Wv, v, BB * NN, DD, DD, 0, 0, 0, 1.f);

    // Scores: per batch [4096,4096] = Q @ K^T * scale  (B = [N,K], trans)
    gemm_h<true><<<dim3(NN / BN, NN / BM, BB), thr>>>(
        q, k, s, NN, NN, DD,
        (size_t)NN * DD, (size_t)NN * DD, (size_t)NN * NN, scale);

    // Row softmax (in place)
    softmax_rows<<<BB * NN, thr>>>(s);

    // Output: per batch [4096,768] = P @ V  (B = [K,N], non-trans)
    gemm_h<false><<<dim3(DD / BN, NN / BM, BB), thr>>>(
        s, v, out, NN, DD, NN,
        (size_t)NN * NN, (size_t)NN * DD, (size_t)NN * DD, 1.f);
}

// round 6
// speedup vs baseline: 2.5503x; 1.5075x over previous
#include <cuda_runtime.h>
#include <cuda_fp16.h>
#include <cstdint>

#define BB 2
#define NN 4096
#define DD 768

constexpr int BM = 128, BN = 128, BK = 32;

// ---------------------------------------------------------------------------
// Scratch
// ---------------------------------------------------------------------------
__device__ __half g_qh[BB * NN * DD];
__device__ __half g_kh[BB * NN * DD];
__device__ __half g_vh[BB * NN * DD];
__device__ __half g_vt[BB * NN * DD];            // V^T per batch [DD, NN]
__device__ float  g_s[(size_t)BB * NN * NN];     // fp32 scores
__device__ __half g_p[(size_t)BB * NN * NN];     // fp16 probs

// ---------------------------------------------------------------------------
// Helpers
// ---------------------------------------------------------------------------
__device__ __forceinline__ uint32_t smem_u32(const void* p) {
    uint32_t a;
    asm("{ .reg .u64 t; cvta.to.shared.u64 t, %1; cvt.u32.u64 %0, t; }" : "=r"(a) : "l"(p));
    return a;
}
__device__ __forceinline__ uint32_t sw64(uint32_t o) { return o ^ ((o >> 3) & 0x30); }

__device__ __forceinline__ void ldm_x4(uint32_t* r, uint32_t a) {
    asm volatile("ldmatrix.sync.aligned.m8n8.x4.shared.b16 {%0,%1,%2,%3}, [%4];"
                 : "=r"(r[0]), "=r"(r[1]), "=r"(r[2]), "=r"(r[3]) : "r"(a));
}
__device__ __forceinline__ void mma16816(float* c, const uint32_t* a, const uint32_t* b) {
    asm volatile(
        "mma.sync.aligned.m16n8k16.row.col.f32.f16.f16.f32 "
        "{%0,%1,%2,%3},{%4,%5,%6,%7},{%8,%9},{%0,%1,%2,%3};"
        : "+f"(c[0]), "+f"(c[1]), "+f"(c[2]), "+f"(c[3])
        : "r"(a[0]), "r"(a[1]), "r"(a[2]), "r"(a[3]), "r"(b[0]), "r"(b[1]));
}
__device__ __forceinline__ uint32_t h2u(__half2 h) { return *(uint32_t*)&h; }
__device__ __forceinline__ void cpa16(uint32_t dst, const void* src) {
    asm volatile("cp.async.cg.shared.global [%0], [%1], 16;" :: "r"(dst), "l"(src));
}

// ---------------------------------------------------------------------------
// Big GEMM: C(fp32) = alpha * A(fp16 [M,K]) @ B(fp16 [N,K])^T
// 4-stage cp.async pipeline, 128x128x32 CTA tile, 8 warps of 64x32.
// SMEM rows: 32 fp16 = 64B, SW64 swizzle; fragments via ldmatrix.x4.
// ---------------------------------------------------------------------------
__global__ __launch_bounds__(256, 2)
void gemm_hh(const __half* __restrict__ Ag, const __half* __restrict__ Bg,
             float* __restrict__ Cg, int M, int Ncols, int K,
             size_t sAs, size_t sBs, size_t sCs, float alpha)
{
    extern __shared__ __align__(1024) __half sm[];
    __half* sA = sm;               // 4 stages x 4096 halfs
    __half* sB = sm + 4 * 4096;

    const int tid  = threadIdx.x;
    const int lane = tid & 31;
    const int warp = tid >> 5;
    const int wm = warp >> 2;      // 0..1 (64 rows)
    const int wn = warp & 3;       // 0..3 (32 cols)
    const int z = blockIdx.z;
    Ag += (size_t)z * sAs;
    Bg += (size_t)z * sBs;
    Cg += (size_t)z * sCs;
    const int m0 = blockIdx.y * BM;
    const int n0 = blockIdx.x * BN;

    float acc[4][4][4];
#pragma unroll
    for (int mi = 0; mi < 4; mi++)
#pragma unroll
        for (int ni = 0; ni < 4; ni++)
#pragma unroll
            for (int r = 0; r < 4; r++) acc[mi][ni][r] = 0.f;

    auto LOAD = [&](int t) {
        const int s = t & 3;
        const int k0 = t * BK;
        const uint32_t da = smem_u32(sA + s * 4096);
        const uint32_t db = smem_u32(sB + s * 4096);
#pragma unroll
        for (int i = 0; i < 2; i++) {
            const int idx = tid + i * 256;
            const int r = idx >> 2, c = idx & 3;
            cpa16(da + sw64(r * 64 + c * 16), Ag + (size_t)(m0 + r) * K + k0 + c * 8);
            cpa16(db + sw64(r * 64 + c * 16), Bg + (size_t)(n0 + r) * K + k0 + c * 8);
        }
        asm volatile("cp.async.commit_group;" ::: "memory");
    };

    // fragment lane addressing
    const int mrow  = wm * 64 + (lane & 15);
    const int acolb = (lane & 16);
    const int nrow  = wn * 32 + (lane & 7) + ((lane & 16) >> 1);
    const int bcolb = (lane & 8) << 1;

    auto KSTEP = [&](int s, int ks) {
        const uint32_t baseA = smem_u32(sA + s * 4096);
        const uint32_t baseB = smem_u32(sB + s * 4096);
        uint32_t a[4][4], b[2][4];
#pragma unroll
        for (int mi = 0; mi < 4; mi++)
            ldm_x4(a[mi], baseA + sw64((mrow + mi * 16) * 64 + ks * 2 + acolb));
#pragma unroll
        for (int n2 = 0; n2 < 2; n2++)
            ldm_x4(b[n2], baseB + sw64((nrow + n2 * 16) * 64 + ks * 2 + bcolb));
#pragma unroll
        for (int mi = 0; mi < 4; mi++)
#pragma unroll
            for (int ni = 0; ni < 4; ni++)
                mma16816(acc[mi][ni], a[mi], &b[ni >> 1][(ni & 1) * 2]);
    };

    const int NT = K / BK;
    LOAD(0); LOAD(1); LOAD(2);
    for (int t = 0; t < NT; t++) {
        asm volatile("cp.async.wait_group 2;" ::: "memory");
        __syncthreads();
        if (t + 3 < NT) LOAD(t + 3);
        else asm volatile("cp.async.commit_group;" ::: "memory");   // keep group count uniform
        const int s = t & 3;
        KSTEP(s, 0);
        KSTEP(s, 16);
    }

    // epilogue
#pragma unroll
    for (int mi = 0; mi < 4; mi++) {
        const int r = m0 + wm * 64 + mi * 16 + (lane >> 2);
#pragma unroll
        for (int ni = 0; ni < 4; ni++) {
            const int c = n0 + wn * 32 + ni * 8 + (lane & 3) * 2;
            *(float2*)(Cg + (size_t)r * Ncols + c) =
                make_float2(alpha * acc[mi][ni][0], alpha * acc[mi][ni][1]);
            *(float2*)(Cg + (size_t)(r + 8) * Ncols + c) =
                make_float2(alpha * acc[mi][ni][2], alpha * acc[mi][ni][3]);
        }
    }
}

// ---------------------------------------------------------------------------
// QKV projection GEMM: C(fp16) = A(fp32 [M,K]) @ B(fp32 [K,N])
// (R5-proven register-staged path; small fraction of runtime)
// ---------------------------------------------------------------------------
__global__ __launch_bounds__(256, 2)
void gemm_qkv(const float* __restrict__ Ag, const float* __restrict__ Bg,
              __half* __restrict__ Cg, int M, int Ncols, int K)
{
    __shared__ __align__(1024) __half sA[2][BM * BK];
    __shared__ __align__(1024) __half sB[2][BN * BK];

    const int tid  = threadIdx.x;
    const int lane = tid & 31;
    const int warp = tid >> 5;
    const int wm = warp >> 2;
    const int wn = warp & 3;
    const int m0 = blockIdx.y * BM;
    const int n0 = blockIdx.x * BN;

    float acc[4][4][4];
#pragma unroll
    for (int mi = 0; mi < 4; mi++)
#pragma unroll
        for (int ni = 0; ni < 4; ni++)
#pragma unroll
            for (int r = 0; r < 4; r++) acc[mi][ni][r] = 0.f;

    float4 fa[4];
    float  fbn[16];
    const int nnf = tid & 127;
    const int q0  = tid >> 7;

    auto LDGA = [&](int t) {
        const int k0 = t * BK;
#pragma unroll
        for (int i = 0; i < 4; i++) {
            const int f = tid + i * 256;
            fa[i] = *(const float4*)(Ag + (size_t)(m0 + (f >> 3)) * K + k0 + (f & 7) * 4);
        }
    };
    auto STSA = [&](int s) {
#pragma unroll
        for (int i = 0; i < 4; i++) {
            const int f = tid + i * 256;
            uint2 u;
            u.x = h2u(__floats2half2_rn(fa[i].x, fa[i].y));
            u.y = h2u(__floats2half2_rn(fa[i].z, fa[i].w));
            *(uint2*)((char*)sA[s] + sw64((f >> 3) * 64 + (f & 7) * 8)) = u;
        }
    };
    auto LDGB = [&](int t) {
        const int k0 = t * BK;
#pragma unroll
        for (int i = 0; i < 4; i++) {
            const int q = q0 + 2 * i;
            const float* src = Bg + (size_t)(k0 + q * 4) * Ncols + n0 + nnf;
            fbn[i * 4 + 0] = src[0];
            fbn[i * 4 + 1] = src[Ncols];
            fbn[i * 4 + 2] = src[2 * Ncols];
            fbn[i * 4 + 3] = src[3 * Ncols];
        }
    };
    auto STSB = [&](int s) {
#pragma unroll
        for (int i = 0; i < 4; i++) {
            const int q = q0 + 2 * i;
            uint2 u;
            u.x = h2u(__floats2half2_rn(fbn[i * 4 + 0], fbn[i * 4 + 1]));
            u.y = h2u(__floats2half2_rn(fbn[i * 4 + 2], fbn[i * 4 + 3]));
            *(uint2*)((char*)sB[s] + sw64(nnf * 64 + q * 8)) = u;
        }
    };

    const int mrow  = wm * 64 + (lane & 15);
    const int acolb = (lane & 16);
    const int nrow  = wn * 32 + (lane & 7) + ((lane & 16) >> 1);
    const int bcolb = (lane & 8) << 1;

    auto KSTEP = [&](int s, int ks) {
        const uint32_t baseA = smem_u32(sA[s]);
        const uint32_t baseB = smem_u32(sB[s]);
        uint32_t a[4][4], b[2][4];
#pragma unroll
        for (int mi = 0; mi < 4; mi++)
            ldm_x4(a[mi], baseA + sw64((mrow + mi * 16) * 64 + ks * 2 + acolb));
#pragma unroll
        for (int n2 = 0; n2 < 2; n2++)
            ldm_x4(b[n2], baseB + sw64((nrow + n2 * 16) * 64 + ks * 2 + bcolb));
#pragma unroll
        for (int mi = 0; mi < 4; mi++)
#pragma unroll
            for (int ni = 0; ni < 4; ni++)
                mma16816(acc[mi][ni], a[mi], &b[ni >> 1][(ni & 1) * 2]);
    };

    LDGA(0); LDGB(0);
    STSA(0); STSB(0);
    __syncthreads();

    const int NT = K / BK;
    for (int t = 0; t < NT; t++) {
        const int s = t & 1;
        const bool more = (t + 1 < NT);
        if (more) LDGA(t + 1);
        KSTEP(s, 0);
        if (more) { STSA(s ^ 1); LDGB(t + 1); }
        KSTEP(s, 16);
        if (more) STSB(s ^ 1);
        __syncthreads();
    }

#pragma unroll
    for (int mi = 0; mi < 4; mi++) {
        const int r = m0 + wm * 64 + mi * 16 + (lane >> 2);
#pragma unroll
        for (int ni = 0; ni < 4; ni++) {
            const int c = n0 + wn * 32 + ni * 8 + (lane & 3) * 2;
            *(__half2*)(Cg + (size_t)r * Ncols + c) =
                __floats2half2_rn(acc[mi][ni][0], acc[mi][ni][1]);
            *(__half2*)(Cg + (size_t)(r + 8) * Ncols + c) =
                __floats2half2_rn(acc[mi][ni][2], acc[mi][ni][3]);
        }
    }
}

// ---------------------------------------------------------------------------
// fp16 transpose per batch: src [NN, DD] -> dst [DD, NN]
// ---------------------------------------------------------------------------
__global__ __launch_bounds__(256)
void transpose_h(const __half* __restrict__ src, __half* __restrict__ dst)
{
    __shared__ __half tile[64][65];
    const int z = blockIdx.z;
    src += (size_t)z * NN * DD;
    dst += (size_t)z * NN * DD;
    const int d0 = blockIdx.x * 64;
    const int t0 = blockIdx.y * 64;
    const int tid = threadIdx.x;

#pragma unroll
    for (int i = 0; i < 8; i++) {
        const int idx = tid + i * 256;
        const int r = idx >> 5, c2 = idx & 31;
        __half2 v = *(const __half2*)(src + (size_t)(t0 + r) * DD + d0 + c2 * 2);
        tile[r][c2 * 2]     = __low2half(v);
        tile[r][c2 * 2 + 1] = __high2half(v);
    }
    __syncthreads();
#pragma unroll
    for (int i = 0; i < 8; i++) {
        const int idx = tid + i * 256;
        const int dr = idx >> 5, c2 = idx & 31;
        __half2 v = __halves2half2(tile[c2 * 2][dr], tile[c2 * 2 + 1][dr]);
        *(__half2*)(dst + (size_t)(d0 + dr) * NN + t0 + c2 * 2) = v;
    }
}

// ---------------------------------------------------------------------------
// Row softmax: fp32 scores in, fp16 probs out. Rows of 4096.
// ---------------------------------------------------------------------------
__global__ __launch_bounds__(256)
void softmax_p(const float* __restrict__ S, __half* __restrict__ P)
{
    const float4* p = (const float4*)(S + (size_t)blockIdx.x * NN);
    __half* o = P + (size_t)blockIdx.x * NN;
    const int t = threadIdx.x;

    float4 v[4];
    float mx = -3.4e38f;
#pragma unroll
    for (int i = 0; i < 4; i++) {
        v[i] = p[t + i * 256];
        mx = fmaxf(mx, fmaxf(fmaxf(v[i].x, v[i].y), fmaxf(v[i].z, v[i].w)));
    }

    __shared__ float shm[8], shs[8];
#pragma unroll
    for (int ofs = 16; ofs; ofs >>= 1) mx = fmaxf(mx, __shfl_xor_sync(0xffffffffu, mx, ofs));
    if ((t & 31) == 0) shm[t >> 5] = mx;
    __syncthreads();
    mx = shm[0];
#pragma unroll
    for (int i = 1; i < 8; i++) mx = fmaxf(mx, shm[i]);

    float sum = 0.f;
#pragma unroll
    for (int i = 0; i < 4; i++) {
        v[i].x = __expf(v[i].x - mx); v[i].y = __expf(v[i].y - mx);
        v[i].z = __expf(v[i].z - mx); v[i].w = __expf(v[i].w - mx);
        sum += v[i].x + v[i].y + v[i].z + v[i].w;
    }
#pragma unroll
    for (int ofs = 16; ofs; ofs >>= 1) sum += __shfl_xor_sync(0xffffffffu, sum, ofs);
    if ((t & 31) == 0) shs[t >> 5] = sum;
    __syncthreads();
    sum = 0.f;
#pragma unroll
    for (int i = 0; i < 8; i++) sum += shs[i];

    const float inv = 1.0f / sum;
#pragma unroll
    for (int i = 0; i < 4; i++) {
        uint2 u;
        u.x = h2u(__floats2half2_rn(v[i].x * inv, v[i].y * inv));
        u.y = h2u(__floats2half2_rn(v[i].z * inv, v[i].w * inv));
        *(uint2*)(o + (t + i * 256) * 4) = u;
    }
}

// ---------------------------------------------------------------------------
extern "C" void kernel_launch(void* const* d_in, const int* in_sizes, int n_in,
                              void* d_out, int out_size)
{
    const float* x  = (const float*)d_in[0];
    const float* Wq = (const float*)d_in[1];
    const float* Wk = (const float*)d_in[2];
    const float* Wv = (const float*)d_in[3];
    float* out = (float*)d_out;

    __half *qh, *kh, *vh, *vt, *ph;
    float* s;
    cudaGetSymbolAddress((void**)&qh, g_qh);
    cudaGetSymbolAddress((void**)&kh, g_kh);
    cudaGetSymbolAddress((void**)&vh, g_vh);
    cudaGetSymbolAddress((void**)&vt, g_vt);
    cudaGetSymbolAddress((void**)&s,  g_s);
    cudaGetSymbolAddress((void**)&ph, g_p);

    const int SMEM = 4 * 2 * BM * BK * 2;   // 65536
    static bool attr_set = false;
    if (!attr_set) {
        cudaFuncSetAttribute(gemm_hh, cudaFuncAttributeMaxDynamicSharedMemorySize, SMEM);
        attr_set = true;
    }

    const float scale = 0.03608439182435161f;  // 1/sqrt(768)
    const dim3 thr(256);

    // QKV projections: [8192,768] @ [768,768] -> fp16
    const dim3 gQKV(DD / BN, (BB * NN) / BM, 1);
    gemm_qkv<<<gQKV, thr>>>(x, Wq, qh, BB * NN, DD, DD);
    gemm_qkv<<<gQKV, thr>>>(x, Wk, kh, BB * NN, DD, DD);
    gemm_qkv<<<gQKV, thr>>>(x, Wv, vh, BB * NN, DD, DD);

    // V^T per batch
    transpose_h<<<dim3(DD / 64, NN / 64, BB), thr>>>(vh, vt);

    // Scores: per batch [4096,4096] = Q @ K^T * scale  (fp32 out)
    gemm_hh<<<dim3(NN / BN, NN / BM, BB), thr, SMEM>>>(
        qh, kh, s, NN, NN, DD,
        (size_t)NN * DD, (size_t)NN * DD, (size_t)NN * NN, scale);

    // Softmax: fp32 -> fp16 probs
    softmax_p<<<BB * NN, thr>>>(s, ph);

    // Output: per batch [4096,768] = P @ V = P @ (V^T)^T  (fp32 out)
    gemm_hh<<<dim3(DD / BN, NN / BM, BB), thr, SMEM>>>(
        ph, vt, out, NN, DD, NN,
        (size_t)NN * NN, (size_t)NN * DD, (size_t)NN * DD, 1.f);
}